// round 3
// baseline (speedup 1.0000x reference)
#include <cuda_runtime.h>
#include <math.h>

// Problem constants
#define Bsz 2
#define Tn  2048
#define En  2048
#define Gn  4
#define Hn  16      // G*QPG
#define Dn  128

// Scratch (alloc-free: __device__ globals)
__device__ float g_Q[(size_t)Bsz * Hn * Tn * Dn];   // (B,H,T,D)
__device__ float g_K[(size_t)Bsz * Gn * Tn * Dn];   // (B,G,T,D)
__device__ float g_V[(size_t)Bsz * Gn * Tn * Dn];   // (B,G,T,D)
__device__ float g_O[(size_t)Bsz * Tn * Hn * Dn];   // (B,T,H*D)

// Sinusoidal PE matching the JAX reference:
// inv_freq = exp(-log(10000)*i/D) with i = 2*(d/2); even d -> sin, odd d -> cos
__device__ __forceinline__ float pe_val(int t, int d) {
    float i2 = (float)(d & ~1);
    float inv = expf(-9.210340371976184f * i2 / 128.0f);  // log(10000)
    float ang = (float)t * inv;
    return (d & 1) ? cosf(ang) : sinf(ang);
}

// ---------------------------------------------------------------------------
// SGEMM: C = A(MxK) @ W(KxN) [+ bias] [+ PE] with mode-specific scatter.
// MODE 0: plain, A = g_O, write to `out` (final wo projection)
// MODE 1: q-projection: + bq + PE, scatter to g_Q (B,H,T,D)
// MODE 2: kv-projection: + bkv, PE on K half, scatter to g_K / g_V (B,G,T,D)
// Tiles: BM=BN=128, BK=16, 256 threads, 8x8 per thread.
// ---------------------------------------------------------------------------
template<int MODE>
__global__ void __launch_bounds__(256, 1) sgemm_k(
    const float* __restrict__ Ain, const float* __restrict__ W,
    const float* __restrict__ bias, float* __restrict__ out,
    int M, int N, int K)
{
    __shared__ float As[16][128];   // transposed A tile: As[k][m]
    __shared__ float Ws[16][128];   // Ws[k][n]

    const float* A = (MODE == 0) ? (const float*)g_O : Ain;

    const int tid = threadIdx.x;
    const int tx = tid & 15, ty = tid >> 4;
    const int bm = blockIdx.y, bn = blockIdx.x;

    const int arow = tid >> 2;           // 0..63
    const int acol = (tid & 3) << 2;     // 0,4,8,12
    const int wrow = tid >> 5;           // 0..7
    const int wcol = (tid & 31) << 2;    // 0..124

    float acc[8][8];
#pragma unroll
    for (int i = 0; i < 8; ++i)
#pragma unroll
        for (int j = 0; j < 8; ++j) acc[i][j] = 0.f;

    for (int k0 = 0; k0 < K; k0 += 16) {
#pragma unroll
        for (int r = 0; r < 2; ++r) {
            float4 v = *(const float4*)(A + (size_t)(bm * 128 + arow + 64 * r) * K + k0 + acol);
            As[acol + 0][arow + 64 * r] = v.x;
            As[acol + 1][arow + 64 * r] = v.y;
            As[acol + 2][arow + 64 * r] = v.z;
            As[acol + 3][arow + 64 * r] = v.w;
        }
#pragma unroll
        for (int r = 0; r < 2; ++r) {
            float4 v = *(const float4*)(W + (size_t)(k0 + wrow + 8 * r) * N + bn * 128 + wcol);
            *(float4*)&Ws[wrow + 8 * r][wcol] = v;
        }
        __syncthreads();

#pragma unroll
        for (int k = 0; k < 16; ++k) {
            float4 a0 = *(const float4*)&As[k][ty * 8];
            float4 a1 = *(const float4*)&As[k][ty * 8 + 4];
            float4 b0 = *(const float4*)&Ws[k][tx * 8];
            float4 b1 = *(const float4*)&Ws[k][tx * 8 + 4];
            float a[8] = {a0.x, a0.y, a0.z, a0.w, a1.x, a1.y, a1.z, a1.w};
            float b[8] = {b0.x, b0.y, b0.z, b0.w, b1.x, b1.y, b1.z, b1.w};
#pragma unroll
            for (int i = 0; i < 8; ++i)
#pragma unroll
                for (int j = 0; j < 8; ++j)
                    acc[i][j] = fmaf(a[i], b[j], acc[i][j]);
        }
        __syncthreads();
    }

    const int gm0 = bm * 128 + ty * 8;
    const int gn0 = bn * 128 + tx * 8;

    if (MODE == 0) {
#pragma unroll
        for (int i = 0; i < 8; ++i) {
            float4 v0 = make_float4(acc[i][0], acc[i][1], acc[i][2], acc[i][3]);
            float4 v1 = make_float4(acc[i][4], acc[i][5], acc[i][6], acc[i][7]);
            *(float4*)(out + (size_t)(gm0 + i) * N + gn0) = v0;
            *(float4*)(out + (size_t)(gm0 + i) * N + gn0 + 4) = v1;
        }
    } else if (MODE == 1) {
#pragma unroll
        for (int i = 0; i < 8; ++i) {
            int gm = gm0 + i;
            int b = gm >> 11;           // / Tn
            int t = gm & (Tn - 1);
#pragma unroll
            for (int j = 0; j < 8; ++j) {
                int gn = gn0 + j;
                int h = gn >> 7, d = gn & 127;
                float val = acc[i][j] + bias[gn] + pe_val(t, d);
                g_Q[(((size_t)(b * Hn + h)) * Tn + t) * Dn + d] = val;
            }
        }
    } else {  // MODE 2
#pragma unroll
        for (int i = 0; i < 8; ++i) {
            int gm = gm0 + i;
            int b = gm >> 11;
            int t = gm & (Tn - 1);
#pragma unroll
            for (int j = 0; j < 8; ++j) {
                int gn = gn0 + j;
                int g = gn >> 8, r = gn & 255;
                float val = acc[i][j] + bias[gn];
                size_t base = (((size_t)(b * Gn + g)) * Tn + t) * Dn;
                if (r < 128) g_K[base + r] = val + pe_val(t, r);
                else         g_V[base + (r - 128)] = val;
            }
        }
    }
}

// ---------------------------------------------------------------------------
// Flash attention: per block (q_tile of 64 rows, one (b,h) head).
// 256 threads = 16x16; thread (ty,tx) owns 4 q rows x (4 S cols / 8 O cols).
// Shared tiles padded to stride 132 / 65 to avoid bank conflicts on the
// row-stride-128 (= 0 mod 32 banks) access patterns.
// ---------------------------------------------------------------------------
#define QSTRIDE 132
#define PSTRIDE 65
#define ATTN_SMEM ((3 * 64 * QSTRIDE + 64 * PSTRIDE) * 4)

__global__ void __launch_bounds__(256, 1) attn_k()
{
    extern __shared__ float sh[];
    float* Qs = sh;                      // 64 x 132
    float* Ks = Qs + 64 * QSTRIDE;       // 64 x 132
    float* Vs = Ks + 64 * QSTRIDE;       // 64 x 132
    float* Ps = Vs + 64 * QSTRIDE;       // 64 x 65

    const int qt = blockIdx.x;           // 0..31 q tiles
    const int bh = blockIdx.y;           // 0..31
    const int b = bh >> 4, h = bh & 15, g = h >> 2;
    const int tid = threadIdx.x, tx = tid & 15, ty = tid >> 4;

    const float* Qp = g_Q + (((size_t)(b * Hn + h)) * Tn + qt * 64) * Dn;
    const float* Kp = g_K + ((size_t)(b * Gn + g)) * Tn * Dn;
    const float* Vp = g_V + ((size_t)(b * Gn + g)) * Tn * Dn;

    // Load Q tile (64 x 128)
    for (int v = tid; v < 64 * 32; v += 256) {
        int r = v >> 5, c = (v & 31) << 2;
        *(float4*)&Qs[r * QSTRIDE + c] = *(const float4*)&Qp[r * 128 + c];
    }

    float m_i[4], l_i[4], o[4][8];
#pragma unroll
    for (int i = 0; i < 4; ++i) {
        m_i[i] = -1e30f; l_i[i] = 0.f;
#pragma unroll
        for (int j = 0; j < 8; ++j) o[i][j] = 0.f;
    }
    const float scale = 0.08838834764831845f;  // 1/sqrt(128)

    for (int kt = 0; kt <= qt; ++kt) {
        __syncthreads();   // protect prior-iter Ks/Vs/Ps reads (and Qs on iter 0)
        const float* Kt = Kp + (size_t)kt * 64 * 128;
        const float* Vt = Vp + (size_t)kt * 64 * 128;
        for (int v = tid; v < 64 * 32; v += 256) {
            int r = v >> 5, c = (v & 31) << 2;
            *(float4*)&Ks[r * QSTRIDE + c] = *(const float4*)&Kt[r * 128 + c];
            *(float4*)&Vs[r * QSTRIDE + c] = *(const float4*)&Vt[r * 128 + c];
        }
        __syncthreads();

        // S = Q K^T  (4x4 per thread)
        float s[4][4];
#pragma unroll
        for (int i = 0; i < 4; ++i)
#pragma unroll
            for (int j = 0; j < 4; ++j) s[i][j] = 0.f;

        for (int d = 0; d < 128; d += 4) {
            float4 qv[4], kvv[4];
#pragma unroll
            for (int i = 0; i < 4; ++i) qv[i] = *(const float4*)&Qs[(ty * 4 + i) * QSTRIDE + d];
#pragma unroll
            for (int j = 0; j < 4; ++j) kvv[j] = *(const float4*)&Ks[(tx * 4 + j) * QSTRIDE + d];
#pragma unroll
            for (int i = 0; i < 4; ++i)
#pragma unroll
                for (int j = 0; j < 4; ++j) {
                    s[i][j] = fmaf(qv[i].x, kvv[j].x, s[i][j]);
                    s[i][j] = fmaf(qv[i].y, kvv[j].y, s[i][j]);
                    s[i][j] = fmaf(qv[i].z, kvv[j].z, s[i][j]);
                    s[i][j] = fmaf(qv[i].w, kvv[j].w, s[i][j]);
                }
        }

        const bool diag = (kt == qt);
#pragma unroll
        for (int i = 0; i < 4; ++i) {
            int qrow = qt * 64 + ty * 4 + i;
            float mloc = -1e30f;
#pragma unroll
            for (int j = 0; j < 4; ++j) {
                float val = s[i][j] * scale;
                if (diag && (kt * 64 + tx * 4 + j) > qrow) val = -1e30f;
                s[i][j] = val;
                mloc = fmaxf(mloc, val);
            }
            // reduce over the 16 lanes sharing this row (xor <16 stays in group)
#pragma unroll
            for (int off = 8; off > 0; off >>= 1)
                mloc = fmaxf(mloc, __shfl_xor_sync(0xffffffffu, mloc, off));
            float mnew = fmaxf(m_i[i], mloc);
            float corr = __expf(m_i[i] - mnew);
            m_i[i] = mnew;
            float psum = 0.f;
#pragma unroll
            for (int j = 0; j < 4; ++j) {
                float p = __expf(s[i][j] - mnew);
                Ps[(ty * 4 + i) * PSTRIDE + tx * 4 + j] = p;
                psum += p;
            }
#pragma unroll
            for (int off = 8; off > 0; off >>= 1)
                psum += __shfl_xor_sync(0xffffffffu, psum, off);
            l_i[i] = l_i[i] * corr + psum;
#pragma unroll
            for (int c = 0; c < 8; ++c) o[i][c] *= corr;
        }
        __syncthreads();

        // O += P @ V  (4 rows x 8 cols per thread)
        for (int sx = 0; sx < 64; ++sx) {
            float4 v0 = *(const float4*)&Vs[sx * QSTRIDE + tx * 8];
            float4 v1 = *(const float4*)&Vs[sx * QSTRIDE + tx * 8 + 4];
#pragma unroll
            for (int i = 0; i < 4; ++i) {
                float p = Ps[(ty * 4 + i) * PSTRIDE + sx];
                o[i][0] = fmaf(p, v0.x, o[i][0]);
                o[i][1] = fmaf(p, v0.y, o[i][1]);
                o[i][2] = fmaf(p, v0.z, o[i][2]);
                o[i][3] = fmaf(p, v0.w, o[i][3]);
                o[i][4] = fmaf(p, v1.x, o[i][4]);
                o[i][5] = fmaf(p, v1.y, o[i][5]);
                o[i][6] = fmaf(p, v1.z, o[i][6]);
                o[i][7] = fmaf(p, v1.w, o[i][7]);
            }
        }
    }

    // Normalize and write to g_O layout (B, T, H*D)
#pragma unroll
    for (int i = 0; i < 4; ++i) {
        float inv = 1.f / l_i[i];
        int t = qt * 64 + ty * 4 + i;
        float4 v0 = make_float4(o[i][0] * inv, o[i][1] * inv, o[i][2] * inv, o[i][3] * inv);
        float4 v1 = make_float4(o[i][4] * inv, o[i][5] * inv, o[i][6] * inv, o[i][7] * inv);
        float* dst = g_O + ((size_t)(b * Tn + t)) * (Hn * Dn) + h * Dn + tx * 8;
        *(float4*)dst = v0;
        *(float4*)(dst + 4) = v1;
    }
}

// ---------------------------------------------------------------------------
extern "C" void kernel_launch(void* const* d_in, const int* in_sizes, int n_in,
                              void* d_out, int out_size)
{
    const float* x   = (const float*)d_in[0];
    const float* wq  = (const float*)d_in[1];
    const float* bq  = (const float*)d_in[2];
    const float* wkv = (const float*)d_in[3];
    const float* bkv = (const float*)d_in[4];
    const float* wo  = (const float*)d_in[5];
    float* out = (float*)d_out;

    const int M = Bsz * Tn;     // 4096
    dim3 blk(256);

    // q = x@wq + bq + PE  -> g_Q
    sgemm_k<1><<<dim3(2048 / 128, M / 128), blk>>>(x, wq, bq, nullptr, M, 2048, En);
    // kv = x@wkv + bkv (+PE on K) -> g_K, g_V
    sgemm_k<2><<<dim3(1024 / 128, M / 128), blk>>>(x, wkv, bkv, nullptr, M, 1024, En);

    // flash attention -> g_O
    cudaFuncSetAttribute(attn_k, cudaFuncAttributeMaxDynamicSharedMemorySize, ATTN_SMEM);
    attn_k<<<dim3(Tn / 64, Bsz * Hn), blk, ATTN_SMEM>>>();

    // out = g_O @ wo
    sgemm_k<0><<<dim3(2048 / 128, M / 128), blk>>>(nullptr, wo, nullptr, out, M, 2048, Hn * Dn);
}

// round 4
// speedup vs baseline: 1.0012x; 1.0012x over previous
#include <cuda_runtime.h>
#include <math.h>

// Problem constants
#define Bsz 2
#define Tn  2048
#define En  2048
#define Gn  4
#define Hn  16      // G*QPG
#define Dn  128

// Scratch (alloc-free: __device__ globals)
__device__ float g_Q[(size_t)Bsz * Hn * Tn * Dn];   // (B,H,T,D)
__device__ float g_K[(size_t)Bsz * Gn * Tn * Dn];   // (B,G,T,D)
__device__ float g_V[(size_t)Bsz * Gn * Tn * Dn];   // (B,G,T,D)
__device__ float g_O[(size_t)Bsz * Tn * Hn * Dn];   // (B,T,H*D)

// Sinusoidal PE matching the JAX reference:
// inv_freq = exp(-log(10000)*i/D) with i = 2*(d/2); even d -> sin, odd d -> cos
__device__ __forceinline__ float pe_val(int t, int d) {
    float i2 = (float)(d & ~1);
    float inv = expf(-9.210340371976184f * i2 / 128.0f);  // log(10000)
    float ang = (float)t * inv;
    return (d & 1) ? cosf(ang) : sinf(ang);
}

// ---------------------------------------------------------------------------
// SGEMM: C = A(MxK) @ W(KxN) [+ bias] [+ PE] with mode-specific scatter.
// MODE 0: plain, A = g_O, write to `out` (final wo projection)
// MODE 1: q-projection: + bq + PE, scatter to g_Q (B,H,T,D)
// MODE 2: kv-projection: + bkv, PE on K half, scatter to g_K / g_V (B,G,T,D)
// Tiles: BM=BN=128, BK=16, 256 threads, 8x8 per thread.
// ---------------------------------------------------------------------------
template<int MODE>
__global__ void __launch_bounds__(256, 1) sgemm_k(
    const float* __restrict__ Ain, const float* __restrict__ W,
    const float* __restrict__ bias, float* __restrict__ out,
    int M, int N, int K)
{
    __shared__ float As[16][128];   // transposed A tile: As[k][m]
    __shared__ float Ws[16][128];   // Ws[k][n]

    const float* A = (MODE == 0) ? (const float*)g_O : Ain;

    const int tid = threadIdx.x;
    const int tx = tid & 15, ty = tid >> 4;
    const int bm = blockIdx.y, bn = blockIdx.x;

    const int arow = tid >> 2;           // 0..63
    const int acol = (tid & 3) << 2;     // 0,4,8,12
    const int wrow = tid >> 5;           // 0..7
    const int wcol = (tid & 31) << 2;    // 0..124

    float acc[8][8];
#pragma unroll
    for (int i = 0; i < 8; ++i)
#pragma unroll
        for (int j = 0; j < 8; ++j) acc[i][j] = 0.f;

    for (int k0 = 0; k0 < K; k0 += 16) {
#pragma unroll
        for (int r = 0; r < 2; ++r) {
            float4 v = *(const float4*)(A + (size_t)(bm * 128 + arow + 64 * r) * K + k0 + acol);
            As[acol + 0][arow + 64 * r] = v.x;
            As[acol + 1][arow + 64 * r] = v.y;
            As[acol + 2][arow + 64 * r] = v.z;
            As[acol + 3][arow + 64 * r] = v.w;
        }
#pragma unroll
        for (int r = 0; r < 2; ++r) {
            float4 v = *(const float4*)(W + (size_t)(k0 + wrow + 8 * r) * N + bn * 128 + wcol);
            *(float4*)&Ws[wrow + 8 * r][wcol] = v;
        }
        __syncthreads();

#pragma unroll
        for (int k = 0; k < 16; ++k) {
            float4 a0 = *(const float4*)&As[k][ty * 8];
            float4 a1 = *(const float4*)&As[k][ty * 8 + 4];
            float4 b0 = *(const float4*)&Ws[k][tx * 8];
            float4 b1 = *(const float4*)&Ws[k][tx * 8 + 4];
            float a[8] = {a0.x, a0.y, a0.z, a0.w, a1.x, a1.y, a1.z, a1.w};
            float b[8] = {b0.x, b0.y, b0.z, b0.w, b1.x, b1.y, b1.z, b1.w};
#pragma unroll
            for (int i = 0; i < 8; ++i)
#pragma unroll
                for (int j = 0; j < 8; ++j)
                    acc[i][j] = fmaf(a[i], b[j], acc[i][j]);
        }
        __syncthreads();
    }

    const int gm0 = bm * 128 + ty * 8;
    const int gn0 = bn * 128 + tx * 8;

    if (MODE == 0) {
#pragma unroll
        for (int i = 0; i < 8; ++i) {
            float4 v0 = make_float4(acc[i][0], acc[i][1], acc[i][2], acc[i][3]);
            float4 v1 = make_float4(acc[i][4], acc[i][5], acc[i][6], acc[i][7]);
            *(float4*)(out + (size_t)(gm0 + i) * N + gn0) = v0;
            *(float4*)(out + (size_t)(gm0 + i) * N + gn0 + 4) = v1;
        }
    } else if (MODE == 1) {
#pragma unroll
        for (int i = 0; i < 8; ++i) {
            int gm = gm0 + i;
            int b = gm >> 11;           // / Tn
            int t = gm & (Tn - 1);
#pragma unroll
            for (int j = 0; j < 8; ++j) {
                int gn = gn0 + j;
                int h = gn >> 7, d = gn & 127;
                float val = acc[i][j] + bias[gn] + pe_val(t, d);
                g_Q[(((size_t)(b * Hn + h)) * Tn + t) * Dn + d] = val;
            }
        }
    } else {  // MODE 2
#pragma unroll
        for (int i = 0; i < 8; ++i) {
            int gm = gm0 + i;
            int b = gm >> 11;
            int t = gm & (Tn - 1);
#pragma unroll
            for (int j = 0; j < 8; ++j) {
                int gn = gn0 + j;
                int g = gn >> 8, r = gn & 255;
                float val = acc[i][j] + bias[gn];
                size_t base = (((size_t)(b * Gn + g)) * Tn + t) * Dn;
                if (r < 128) g_K[base + r] = val + pe_val(t, r);
                else         g_V[base + (r - 128)] = val;
            }
        }
    }
}

// ---------------------------------------------------------------------------
// Flash attention: per block (q_tile of 64 rows, one (b,h) head).
// 256 threads = 16x16; thread (ty,tx) owns 4 q rows x (4 S cols / 8 O cols).
// Shared tiles padded to stride 132 / 65 to avoid bank conflicts on the
// row-stride-128 (= 0 mod 32 banks) access patterns.
// ---------------------------------------------------------------------------
#define QSTRIDE 132
#define PSTRIDE 65
#define ATTN_SMEM ((3 * 64 * QSTRIDE + 64 * PSTRIDE) * 4)

__global__ void __launch_bounds__(256, 1) attn_k()
{
    extern __shared__ float sh[];
    float* Qs = sh;                      // 64 x 132
    float* Ks = Qs + 64 * QSTRIDE;       // 64 x 132
    float* Vs = Ks + 64 * QSTRIDE;       // 64 x 132
    float* Ps = Vs + 64 * QSTRIDE;       // 64 x 65

    const int qt = blockIdx.x;           // 0..31 q tiles
    const int bh = blockIdx.y;           // 0..31
    const int b = bh >> 4, h = bh & 15, g = h >> 2;
    const int tid = threadIdx.x, tx = tid & 15, ty = tid >> 4;

    const float* Qp = g_Q + (((size_t)(b * Hn + h)) * Tn + qt * 64) * Dn;
    const float* Kp = g_K + ((size_t)(b * Gn + g)) * Tn * Dn;
    const float* Vp = g_V + ((size_t)(b * Gn + g)) * Tn * Dn;

    // Load Q tile (64 x 128)
    for (int v = tid; v < 64 * 32; v += 256) {
        int r = v >> 5, c = (v & 31) << 2;
        *(float4*)&Qs[r * QSTRIDE + c] = *(const float4*)&Qp[r * 128 + c];
    }

    float m_i[4], l_i[4], o[4][8];
#pragma unroll
    for (int i = 0; i < 4; ++i) {
        m_i[i] = -1e30f; l_i[i] = 0.f;
#pragma unroll
        for (int j = 0; j < 8; ++j) o[i][j] = 0.f;
    }
    const float scale = 0.08838834764831845f;  // 1/sqrt(128)

    for (int kt = 0; kt <= qt; ++kt) {
        __syncthreads();   // protect prior-iter Ks/Vs/Ps reads (and Qs on iter 0)
        const float* Kt = Kp + (size_t)kt * 64 * 128;
        const float* Vt = Vp + (size_t)kt * 64 * 128;
        for (int v = tid; v < 64 * 32; v += 256) {
            int r = v >> 5, c = (v & 31) << 2;
            *(float4*)&Ks[r * QSTRIDE + c] = *(const float4*)&Kt[r * 128 + c];
            *(float4*)&Vs[r * QSTRIDE + c] = *(const float4*)&Vt[r * 128 + c];
        }
        __syncthreads();

        // S = Q K^T  (4x4 per thread)
        float s[4][4];
#pragma unroll
        for (int i = 0; i < 4; ++i)
#pragma unroll
            for (int j = 0; j < 4; ++j) s[i][j] = 0.f;

        for (int d = 0; d < 128; d += 4) {
            float4 qv[4], kvv[4];
#pragma unroll
            for (int i = 0; i < 4; ++i) qv[i] = *(const float4*)&Qs[(ty * 4 + i) * QSTRIDE + d];
#pragma unroll
            for (int j = 0; j < 4; ++j) kvv[j] = *(const float4*)&Ks[(tx * 4 + j) * QSTRIDE + d];
#pragma unroll
            for (int i = 0; i < 4; ++i)
#pragma unroll
                for (int j = 0; j < 4; ++j) {
                    s[i][j] = fmaf(qv[i].x, kvv[j].x, s[i][j]);
                    s[i][j] = fmaf(qv[i].y, kvv[j].y, s[i][j]);
                    s[i][j] = fmaf(qv[i].z, kvv[j].z, s[i][j]);
                    s[i][j] = fmaf(qv[i].w, kvv[j].w, s[i][j]);
                }
        }

        const bool diag = (kt == qt);
#pragma unroll
        for (int i = 0; i < 4; ++i) {
            int qrow = qt * 64 + ty * 4 + i;
            float mloc = -1e30f;
#pragma unroll
            for (int j = 0; j < 4; ++j) {
                float val = s[i][j] * scale;
                if (diag && (kt * 64 + tx * 4 + j) > qrow) val = -1e30f;
                s[i][j] = val;
                mloc = fmaxf(mloc, val);
            }
            // reduce over the 16 lanes sharing this row (xor <16 stays in group)
#pragma unroll
            for (int off = 8; off > 0; off >>= 1)
                mloc = fmaxf(mloc, __shfl_xor_sync(0xffffffffu, mloc, off));
            float mnew = fmaxf(m_i[i], mloc);
            float corr = __expf(m_i[i] - mnew);
            m_i[i] = mnew;
            float psum = 0.f;
#pragma unroll
            for (int j = 0; j < 4; ++j) {
                float p = __expf(s[i][j] - mnew);
                Ps[(ty * 4 + i) * PSTRIDE + tx * 4 + j] = p;
                psum += p;
            }
#pragma unroll
            for (int off = 8; off > 0; off >>= 1)
                psum += __shfl_xor_sync(0xffffffffu, psum, off);
            l_i[i] = l_i[i] * corr + psum;
#pragma unroll
            for (int c = 0; c < 8; ++c) o[i][c] *= corr;
        }
        __syncthreads();

        // O += P @ V  (4 rows x 8 cols per thread)
        for (int sx = 0; sx < 64; ++sx) {
            float4 v0 = *(const float4*)&Vs[sx * QSTRIDE + tx * 8];
            float4 v1 = *(const float4*)&Vs[sx * QSTRIDE + tx * 8 + 4];
#pragma unroll
            for (int i = 0; i < 4; ++i) {
                float p = Ps[(ty * 4 + i) * PSTRIDE + sx];
                o[i][0] = fmaf(p, v0.x, o[i][0]);
                o[i][1] = fmaf(p, v0.y, o[i][1]);
                o[i][2] = fmaf(p, v0.z, o[i][2]);
                o[i][3] = fmaf(p, v0.w, o[i][3]);
                o[i][4] = fmaf(p, v1.x, o[i][4]);
                o[i][5] = fmaf(p, v1.y, o[i][5]);
                o[i][6] = fmaf(p, v1.z, o[i][6]);
                o[i][7] = fmaf(p, v1.w, o[i][7]);
            }
        }
    }

    // Normalize and write to g_O layout (B, T, H*D)
#pragma unroll
    for (int i = 0; i < 4; ++i) {
        float inv = 1.f / l_i[i];
        int t = qt * 64 + ty * 4 + i;
        float4 v0 = make_float4(o[i][0] * inv, o[i][1] * inv, o[i][2] * inv, o[i][3] * inv);
        float4 v1 = make_float4(o[i][4] * inv, o[i][5] * inv, o[i][6] * inv, o[i][7] * inv);
        float* dst = g_O + ((size_t)(b * Tn + t)) * (Hn * Dn) + h * Dn + tx * 8;
        *(float4*)dst = v0;
        *(float4*)(dst + 4) = v1;
    }
}

// ---------------------------------------------------------------------------
extern "C" void kernel_launch(void* const* d_in, const int* in_sizes, int n_in,
                              void* d_out, int out_size)
{
    const float* x   = (const float*)d_in[0];
    const float* wq  = (const float*)d_in[1];
    const float* bq  = (const float*)d_in[2];
    const float* wkv = (const float*)d_in[3];
    const float* bkv = (const float*)d_in[4];
    const float* wo  = (const float*)d_in[5];
    float* out = (float*)d_out;

    const int M = Bsz * Tn;     // 4096
    dim3 blk(256);

    // q = x@wq + bq + PE  -> g_Q
    sgemm_k<1><<<dim3(2048 / 128, M / 128), blk>>>(x, wq, bq, nullptr, M, 2048, En);
    // kv = x@wkv + bkv (+PE on K) -> g_K, g_V
    sgemm_k<2><<<dim3(1024 / 128, M / 128), blk>>>(x, wkv, bkv, nullptr, M, 1024, En);

    // flash attention -> g_O
    cudaFuncSetAttribute(attn_k, cudaFuncAttributeMaxDynamicSharedMemorySize, ATTN_SMEM);
    attn_k<<<dim3(Tn / 64, Bsz * Hn), blk, ATTN_SMEM>>>();

    // out = g_O @ wo
    sgemm_k<0><<<dim3(2048 / 128, M / 128), blk>>>(nullptr, wo, nullptr, out, M, 2048, Hn * Dn);
}